// round 1
// baseline (speedup 1.0000x reference)
#include <cuda_runtime.h>

// ---------------------------------------------------------------------------
// Problem: Elman RNN (relu), B=64, T=512, I=64, H=1024, O=64
// out = [ hidden_list (B,T,H) | output_list (B,T,O) | h_last (1,B,H) ]
// ---------------------------------------------------------------------------

#define B_   64
#define T_   512
#define I_   64
#define H_   1024
#define O_   64

#define HID_OFF  0
#define OUT_OFF  (B_ * T_ * H_)              // 33554432
#define HL_OFF   (OUT_OFF + B_ * T_ * O_)    // 35651584

#define NBLK 128        // persistent blocks for recurrence (<= 148 SMs, 1/SM)
#define TB   128        // threads per recurrence block

// scratch: h double buffer + grid barrier state
__device__ float    g_hbuf[2][B_ * H_];
__device__ unsigned g_count = 0;
__device__ unsigned g_gen   = 0;

// packed f32x2 FMA (sm_103a): d.lo = fma(a.lo,b.lo,c.lo); d.hi likewise
__device__ __forceinline__ unsigned long long f2fma(unsigned long long a,
                                                    unsigned long long b,
                                                    unsigned long long c) {
    unsigned long long d;
    asm("fma.rn.f32x2 %0, %1, %2, %3;" : "=l"(d) : "l"(a), "l"(b), "l"(c));
    return d;
}

__device__ __forceinline__ float pairsum(unsigned long long a) {
    float lo = __uint_as_float((unsigned)(a & 0xffffffffull));
    float hi = __uint_as_float((unsigned)(a >> 32));
    return lo + hi;
}

// ---------------------------------------------------------------------------
// Kernel A: xw[bt][h] = x[bt]·W_ih[h] + b_ih[h] + b_hh[h]  -> hidden region
// M=32768, N=1024, K=64. Block tile 64x64, 256 threads, 4x4 register tiles.
// ---------------------------------------------------------------------------
__global__ void __launch_bounds__(256) xw_kernel(
    const float* __restrict__ x, const float* __restrict__ Wih,
    const float* __restrict__ bih, const float* __restrict__ bhh,
    float* __restrict__ hid_out)
{
    __shared__ float xs[64 * 65];
    __shared__ float ws[64 * 65];

    const int tid = threadIdx.x;
    const int hb  = blockIdx.x * 64;
    const int btb = blockIdx.y * 64;

    #pragma unroll
    for (int i = tid; i < 64 * 64; i += 256) {
        int r = i >> 6, c = i & 63;
        xs[r * 65 + c] = x[(btb + r) * 64 + c];
        ws[r * 65 + c] = Wih[(hb + r) * 64 + c];
    }
    __syncthreads();

    const int tx = tid & 15, ty = tid >> 4;
    float acc[4][4] = {};

    #pragma unroll 8
    for (int k = 0; k < 64; ++k) {
        float a0 = xs[(ty     ) * 65 + k];
        float a1 = xs[(ty + 16) * 65 + k];
        float a2 = xs[(ty + 32) * 65 + k];
        float a3 = xs[(ty + 48) * 65 + k];
        float b0 = ws[(tx     ) * 65 + k];
        float b1 = ws[(tx + 16) * 65 + k];
        float b2 = ws[(tx + 32) * 65 + k];
        float b3 = ws[(tx + 48) * 65 + k];
        acc[0][0] += a0 * b0; acc[0][1] += a0 * b1; acc[0][2] += a0 * b2; acc[0][3] += a0 * b3;
        acc[1][0] += a1 * b0; acc[1][1] += a1 * b1; acc[1][2] += a1 * b2; acc[1][3] += a1 * b3;
        acc[2][0] += a2 * b0; acc[2][1] += a2 * b1; acc[2][2] += a2 * b2; acc[2][3] += a2 * b3;
        acc[3][0] += a3 * b0; acc[3][1] += a3 * b1; acc[3][2] += a3 * b2; acc[3][3] += a3 * b3;
    }

    #pragma unroll
    for (int j = 0; j < 4; ++j) {
        int h = hb + tx + 16 * j;
        float bb = bih[h] + bhh[h];
        #pragma unroll
        for (int i = 0; i < 4; ++i) {
            int bt = btb + ty + 16 * i;
            hid_out[bt * H_ + h] = acc[i][j] + bb;
        }
    }
}

// ---------------------------------------------------------------------------
// Kernel B: persistent recurrence. 128 blocks = 4 batch-groups x 32 col-groups
// Each block: W_hh slice (32 x 1024) resident in SMEM for all 512 steps.
// Per step: stage 16-batch h slice to SMEM, 2x2 register tile, f32x2 FMAs,
// relu-epilogue writes hidden_list + h ping-pong buffer, then grid barrier.
// ---------------------------------------------------------------------------
__global__ void __launch_bounds__(TB, 1) rnn_recur(
    const float* __restrict__ hid_in,     // (1,B,H) initial hidden
    const float* __restrict__ Whh,        // (H,H)
    float* __restrict__ out)              // d_out base
{
    extern __shared__ float4 sm[];
    float4* w4 = sm;               // [32][257] float4  (128KB + pad)
    float4* h4 = sm + 32 * 257;    // [16][257] float4  (64KB + pad)

    const int tid = threadIdx.x;
    const int bi  = blockIdx.x >> 5;   // 0..3  batch group
    const int ci  = blockIdx.x & 31;   // 0..31 col group
    const int b0  = bi * 16;
    const int c0  = ci * 32;

    // preload W_hh slice: rows c0..c0+31 (1024 floats each)
    const float4* Whh4 = (const float4*)Whh;
    #pragma unroll 4
    for (int i = tid; i < 32 * 256; i += TB) {
        int c = i >> 8, k4 = i & 255;
        w4[c * 257 + k4] = __ldg(&Whh4[(c0 + c) * 256 + k4]);
    }

    const int mth = tid & 7;        // batch position
    const int nth = tid >> 3;       // 0..15 col-pair position
    const int bl0 = mth, bl1 = mth + 8;
    const int cl  = nth * 2;

    float* hid_out = out + HID_OFF;
    float* hlast   = out + HL_OFF;

    const ulonglong2* hp0 = (const ulonglong2*)&h4[bl0 * 257];
    const ulonglong2* hp1 = (const ulonglong2*)&h4[bl1 * 257];
    const ulonglong2* wp0 = (const ulonglong2*)&w4[(cl    ) * 257];
    const ulonglong2* wp1 = (const ulonglong2*)&w4[(cl + 1) * 257];

    for (int s = 0; s < T_; ++s) {
        // ---- stage h slice (16 x 1024 floats) from L2 (coherent path) ----
        const float4* hsrc = (s == 0) ? (const float4*)hid_in
                                      : (const float4*)g_hbuf[(s - 1) & 1];
        #pragma unroll 4
        for (int i = tid; i < 16 * 256; i += TB) {
            int b = i >> 8, k4 = i & 255;
            h4[b * 257 + k4] = __ldcg(&hsrc[(b0 + b) * 256 + k4]);
        }
        __syncthreads();

        // ---- 2x2 tile dot over K=1024 using packed f32x2 FMAs ----
        unsigned long long a00 = 0, a01 = 0, a10 = 0, a11 = 0;
        #pragma unroll 8
        for (int k4 = 0; k4 < 256; ++k4) {
            ulonglong2 ha = hp0[k4];
            ulonglong2 hb = hp1[k4];
            ulonglong2 wa = wp0[k4];
            ulonglong2 wb = wp1[k4];
            a00 = f2fma(ha.x, wa.x, a00); a00 = f2fma(ha.y, wa.y, a00);
            a01 = f2fma(ha.x, wb.x, a01); a01 = f2fma(ha.y, wb.y, a01);
            a10 = f2fma(hb.x, wa.x, a10); a10 = f2fma(hb.y, wa.y, a10);
            a11 = f2fma(hb.x, wb.x, a11); a11 = f2fma(hb.y, wb.y, a11);
        }

        float v00 = pairsum(a00), v01 = pairsum(a01);
        float v10 = pairsum(a10), v11 = pairsum(a11);

        // ---- epilogue: relu(xw + dot), write hidden_list + ping-pong h ----
        const int gc = c0 + cl;
        float* hnew = g_hbuf[s & 1];
        {
            int gb = b0 + bl0;
            float* p = hid_out + ((gb << 9) + s) * H_ + gc;   // gb*512+t
            float2 xw = *(float2*)p;
            float r0 = fmaxf(xw.x + v00, 0.0f);
            float r1 = fmaxf(xw.y + v01, 0.0f);
            *(float2*)p = make_float2(r0, r1);
            *(float2*)(hnew + (gb << 10) + gc) = make_float2(r0, r1);
            if (s == T_ - 1) *(float2*)(hlast + (gb << 10) + gc) = make_float2(r0, r1);
        }
        {
            int gb = b0 + bl1;
            float* p = hid_out + ((gb << 9) + s) * H_ + gc;
            float2 xw = *(float2*)p;
            float r0 = fmaxf(xw.x + v10, 0.0f);
            float r1 = fmaxf(xw.y + v11, 0.0f);
            *(float2*)p = make_float2(r0, r1);
            *(float2*)(hnew + (gb << 10) + gc) = make_float2(r0, r1);
            if (s == T_ - 1) *(float2*)(hlast + (gb << 10) + gc) = make_float2(r0, r1);
        }

        // ---- grid barrier (sense-reversal via generation counter) ----
        __threadfence();          // publish this thread's h writes to L2/GPU
        __syncthreads();          // all threads of this block fenced
        if (tid == 0) {
            unsigned my = *((volatile unsigned*)&g_gen);
            if (atomicAdd(&g_count, 1) == NBLK - 1) {
                g_count = 0;
                __threadfence();
                atomicAdd(&g_gen, 1);     // release
            } else {
                while (*((volatile unsigned*)&g_gen) == my) { }
            }
        }
        __syncthreads();
    }
}

// ---------------------------------------------------------------------------
// Kernel C: output_list[bt][o] = hid[bt]·W_out[o] + b_out[o]
// M=32768, N=64, K=1024. Block tile 128x64, 256 threads, 8x4 register tiles.
// ---------------------------------------------------------------------------
__global__ void __launch_bounds__(256) out_kernel(
    const float* __restrict__ hid, const float* __restrict__ Wout,
    const float* __restrict__ bout, float* __restrict__ outp)
{
    __shared__ float hs[128 * 33];
    __shared__ float ws2[64 * 33];

    const int tid = threadIdx.x;
    const int btb = blockIdx.x * 128;
    const int tx = tid & 15, ty = tid >> 4;

    float acc[8][4] = {};

    for (int kc = 0; kc < H_; kc += 32) {
        #pragma unroll
        for (int i = tid; i < 128 * 32; i += 256) {
            int r = i >> 5, c = i & 31;
            hs[r * 33 + c] = hid[(btb + r) * H_ + kc + c];
        }
        #pragma unroll
        for (int i = tid; i < 64 * 32; i += 256) {
            int r = i >> 5, c = i & 31;
            ws2[r * 33 + c] = Wout[r * H_ + kc + c];
        }
        __syncthreads();

        #pragma unroll 8
        for (int k = 0; k < 32; ++k) {
            float a[8], b[4];
            #pragma unroll
            for (int i = 0; i < 8; ++i) a[i] = hs[(ty + 16 * i) * 33 + k];
            #pragma unroll
            for (int j = 0; j < 4; ++j) b[j] = ws2[(tx + 16 * j) * 33 + k];
            #pragma unroll
            for (int i = 0; i < 8; ++i)
                #pragma unroll
                for (int j = 0; j < 4; ++j)
                    acc[i][j] += a[i] * b[j];
        }
        __syncthreads();
    }

    #pragma unroll
    for (int j = 0; j < 4; ++j) {
        int o = tx + 16 * j;
        float bb = bout[o];
        #pragma unroll
        for (int i = 0; i < 8; ++i)
            outp[(btb + ty + 16 * i) * O_ + o] = acc[i][j] + bb;
    }
}

// ---------------------------------------------------------------------------
extern "C" void kernel_launch(void* const* d_in, const int* in_sizes, int n_in,
                              void* d_out, int out_size) {
    const float* x      = (const float*)d_in[0];
    const float* hidden = (const float*)d_in[1];
    const float* W_ih   = (const float*)d_in[2];
    const float* W_hh   = (const float*)d_in[3];
    const float* b_ih   = (const float*)d_in[4];
    const float* b_hh   = (const float*)d_in[5];
    const float* W_out  = (const float*)d_in[6];
    const float* b_out  = (const float*)d_in[7];
    float* out = (float*)d_out;

    // A: xw into hidden_list region (recurrence overwrites it in place)
    dim3 gA(H_ / 64, (B_ * T_) / 64);   // 16 x 512
    xw_kernel<<<gA, 256>>>(x, W_ih, b_ih, b_hh, out + HID_OFF);

    // B: persistent recurrence (128 blocks, 1/SM, custom grid barrier)
    size_t smemB = (size_t)(32 * 257 + 16 * 257) * sizeof(float4);  // 197376 B
    cudaFuncSetAttribute(rnn_recur, cudaFuncAttributeMaxDynamicSharedMemorySize,
                         (int)smemB);
    rnn_recur<<<NBLK, TB, smemB>>>(hidden, W_hh, out);

    // C: output projection
    out_kernel<<<(B_ * T_) / 128, 256>>>(out + HID_OFF, W_out, b_out, out + OUT_OFF);
}

// round 2
// speedup vs baseline: 1.5439x; 1.5439x over previous
#include <cuda_runtime.h>

// ---------------------------------------------------------------------------
// Elman RNN (relu), B=64, T=512, I=64, H=1024, O=64
// out = [ hidden_list (B,T,H) | output_list (B,T,O) | h_last (1,B,H) ]
// ---------------------------------------------------------------------------

#define B_   64
#define T_   512
#define I_   64
#define H_   1024
#define O_   64

#define HID_OFF  0
#define OUT_OFF  (B_ * T_ * H_)              // 33554432
#define HL_OFF   (OUT_OFF + B_ * T_ * O_)    // 35651584

#define NBLK 128        // persistent blocks (1/SM)
#define TB   128        // threads per recurrence block

// SMEM layout constants (floats)
#define CH   66         // k-chunk stride: 64 + 2 pad (8B bank shift per chunk)
#define HR   1060       // row stride: 16*CH=1056 + 4 (keeps 16B alignment)
#define RST  516        // reduction row stride: 512 + 4

// scratch: h double buffer + grid barrier state
__device__ float    g_hbuf[2][B_ * H_];
__device__ unsigned g_count = 0;
__device__ unsigned g_gen   = 0;

typedef unsigned long long ull;

// packed f32x2 FMA (sm_103a)
__device__ __forceinline__ ull f2fma(ull a, ull b, ull c) {
    ull d;
    asm("fma.rn.f32x2 %0, %1, %2, %3;" : "=l"(d) : "l"(a), "l"(b), "l"(c));
    return d;
}

__device__ __forceinline__ float pairsum(ull a) {
    float lo = __uint_as_float((unsigned)(a & 0xffffffffull));
    float hi = __uint_as_float((unsigned)(a >> 32));
    return lo + hi;
}

// ---------------------------------------------------------------------------
// Kernel A: xw[bt][h] = x[bt]·W_ih[h] + b_ih[h] + b_hh[h]  -> hidden region
// ---------------------------------------------------------------------------
__global__ void __launch_bounds__(256) xw_kernel(
    const float* __restrict__ x, const float* __restrict__ Wih,
    const float* __restrict__ bih, const float* __restrict__ bhh,
    float* __restrict__ hid_out)
{
    __shared__ float xs[64 * 65];
    __shared__ float ws[64 * 65];

    const int tid = threadIdx.x;
    const int hb  = blockIdx.x * 64;
    const int btb = blockIdx.y * 64;

    #pragma unroll
    for (int i = tid; i < 64 * 64; i += 256) {
        int r = i >> 6, c = i & 63;
        xs[r * 65 + c] = x[(btb + r) * 64 + c];
        ws[r * 65 + c] = Wih[(hb + r) * 64 + c];
    }
    __syncthreads();

    const int tx = tid & 15, ty = tid >> 4;
    float acc[4][4] = {};

    #pragma unroll 8
    for (int k = 0; k < 64; ++k) {
        float a0 = xs[(ty     ) * 65 + k];
        float a1 = xs[(ty + 16) * 65 + k];
        float a2 = xs[(ty + 32) * 65 + k];
        float a3 = xs[(ty + 48) * 65 + k];
        float b0 = ws[(tx     ) * 65 + k];
        float b1 = ws[(tx + 16) * 65 + k];
        float b2 = ws[(tx + 32) * 65 + k];
        float b3 = ws[(tx + 48) * 65 + k];
        acc[0][0] += a0 * b0; acc[0][1] += a0 * b1; acc[0][2] += a0 * b2; acc[0][3] += a0 * b3;
        acc[1][0] += a1 * b0; acc[1][1] += a1 * b1; acc[1][2] += a1 * b2; acc[1][3] += a1 * b3;
        acc[2][0] += a2 * b0; acc[2][1] += a2 * b1; acc[2][2] += a2 * b2; acc[2][3] += a2 * b3;
        acc[3][0] += a3 * b0; acc[3][1] += a3 * b1; acc[3][2] += a3 * b2; acc[3][3] += a3 * b3;
    }

    #pragma unroll
    for (int j = 0; j < 4; ++j) {
        int h = hb + tx + 16 * j;
        float bb = bih[h] + bhh[h];
        #pragma unroll
        for (int i = 0; i < 4; ++i) {
            int bt = btb + ty + 16 * i;
            hid_out[bt * H_ + h] = acc[i][j] + bb;
        }
    }
}

// ---------------------------------------------------------------------------
// Kernel B: persistent recurrence.
// 128 blocks = 4 batch-groups(16) x 32 col-groups(32).
// Thread (p, kc): p = tile position (pm in {0,1} batch-octet, pn in 0..3
// col-octet), kc = K-chunk of 64. Each thread: 8x8 f32x2-accumulated tile
// over its K-chunk (1 B/FMA SMEM traffic), then 16-way in-block reduction.
// ---------------------------------------------------------------------------
__global__ void __launch_bounds__(TB, 1) rnn_recur(
    const float* __restrict__ hid_in,
    const float* __restrict__ Whh,
    float* __restrict__ out)
{
    extern __shared__ float sm[];
    float* wsm = sm;                 // 32 rows x HR floats (~135.7 KB)
    float* hsm = sm + 32 * HR;       // 16 rows x HR floats (~67.8 KB)
    float* red = hsm;                // reduction buffer aliases h staging

    const int tid = threadIdx.x;
    const int bi  = blockIdx.x >> 5;   // batch group
    const int ci  = blockIdx.x & 31;   // col group
    const int b0  = bi * 16;
    const int c0  = ci * 32;

    const int kc = tid & 15;           // K-chunk 0..15
    const int p  = tid >> 4;           // tile position 0..7
    const int pm = p & 1;              // batch octet
    const int pn = p >> 1;             // col octet

    // ---- stage W_hh slice once: rows c0..c0+31, chunked layout ----
    const float2* W2 = (const float2*)Whh;
    #pragma unroll 4
    for (int i = tid; i < 32 * 512; i += TB) {
        int r = i >> 9, q = i & 511;          // q = float2 index in row
        int kcs = q >> 5, kk2 = q & 31;
        *(float2*)&wsm[r * HR + kcs * CH + kk2 * 2] = __ldg(&W2[(c0 + r) * 512 + q]);
    }

    const float* hb_ = hsm + pm * 8 * HR + kc * CH;
    const float* wb_ = wsm + pn * 8 * HR + kc * CH;

    float* hid_out = out + HID_OFF;
    float* hlast   = out + HL_OFF;

    const int gb = b0 + (tid >> 3);       // epilogue batch
    const int gc = c0 + (tid & 7) * 4;    // epilogue col (float4 aligned)

    for (int s = 0; s < T_; ++s) {
        // prefetch xw for this thread's epilogue outputs (hides DRAM latency)
        float4 xwv = __ldcg((const float4*)&hid_out[((size_t)gb * T_ + s) * H_ + gc]);

        // ---- stage h slice (16 x 1024) into chunked SMEM layout ----
        const float2* hsrc = (s == 0) ? (const float2*)hid_in
                                      : (const float2*)g_hbuf[(s - 1) & 1];
        #pragma unroll 8
        for (int i = tid; i < 16 * 512; i += TB) {
            int r = i >> 9, q = i & 511;
            int kcs = q >> 5, kk2 = q & 31;
            *(float2*)&hsm[r * HR + kcs * CH + kk2 * 2] = __ldcg(&hsrc[(b0 + r) * 512 + q]);
        }
        __syncthreads();

        // ---- 8x8 tile over private K-chunk of 64, f32x2 FMAs ----
        ull acc[64];
        #pragma unroll
        for (int i = 0; i < 64; ++i) acc[i] = 0ull;

        for (int k2 = 0; k2 < 32; ++k2) {
            ull hv[8];
            #pragma unroll
            for (int i = 0; i < 8; ++i)
                hv[i] = *(const ull*)(hb_ + i * HR + k2 * 2);
            ull wv[4];
            #pragma unroll
            for (int j = 0; j < 4; ++j)
                wv[j] = *(const ull*)(wb_ + j * HR + k2 * 2);
            #pragma unroll
            for (int i = 0; i < 8; ++i)
                #pragma unroll
                for (int j = 0; j < 4; ++j)
                    acc[i * 8 + j] = f2fma(hv[i], wv[j], acc[i * 8 + j]);
            #pragma unroll
            for (int j = 0; j < 4; ++j)
                wv[j] = *(const ull*)(wb_ + (j + 4) * HR + k2 * 2);
            #pragma unroll
            for (int i = 0; i < 8; ++i)
                #pragma unroll
                for (int j = 0; j < 4; ++j)
                    acc[i * 8 + j + 4] = f2fma(hv[i], wv[j], acc[i * 8 + j + 4]);
        }
        __syncthreads();   // h reads done before reduction buffer overwrite

        // ---- write partials: red[kc][o] ----
        #pragma unroll
        for (int i = 0; i < 8; ++i)
            #pragma unroll
            for (int j = 0; j < 8; ++j) {
                int o = (pm * 8 + i) * 32 + pn * 8 + j;
                red[kc * RST + o] = pairsum(acc[i * 8 + j]);
            }
        __syncthreads();

        // ---- 16-way reduction, 4 outputs per thread (float4) ----
        float4 sum = make_float4(0.f, 0.f, 0.f, 0.f);
        #pragma unroll
        for (int r = 0; r < 16; ++r) {
            float4 v = *(const float4*)&red[r * RST + tid * 4];
            sum.x += v.x; sum.y += v.y; sum.z += v.z; sum.w += v.w;
        }

        float4 rl;
        rl.x = fmaxf(xwv.x + sum.x, 0.0f);
        rl.y = fmaxf(xwv.y + sum.y, 0.0f);
        rl.z = fmaxf(xwv.z + sum.z, 0.0f);
        rl.w = fmaxf(xwv.w + sum.w, 0.0f);

        *(float4*)&hid_out[((size_t)gb * T_ + s) * H_ + gc] = rl;
        *(float4*)&g_hbuf[s & 1][gb * H_ + gc] = rl;
        if (s == T_ - 1)
            *(float4*)&hlast[gb * H_ + gc] = rl;

        // ---- grid barrier (skip after the last step) ----
        if (s != T_ - 1) {
            __threadfence();
            __syncthreads();
            if (tid == 0) {
                unsigned my = *((volatile unsigned*)&g_gen);
                if (atomicAdd(&g_count, 1) == NBLK - 1) {
                    g_count = 0;
                    __threadfence();
                    atomicAdd(&g_gen, 1);
                } else {
                    while (*((volatile unsigned*)&g_gen) == my) { }
                }
            }
            __syncthreads();
        }
    }
}

// ---------------------------------------------------------------------------
// Kernel C: output_list[bt][o] = hid[bt]·W_out[o] + b_out[o]
// ---------------------------------------------------------------------------
__global__ void __launch_bounds__(256) out_kernel(
    const float* __restrict__ hid, const float* __restrict__ Wout,
    const float* __restrict__ bout, float* __restrict__ outp)
{
    __shared__ float hs[128 * 33];
    __shared__ float ws2[64 * 33];

    const int tid = threadIdx.x;
    const int btb = blockIdx.x * 128;
    const int tx = tid & 15, ty = tid >> 4;

    float acc[8][4] = {};

    for (int kc2 = 0; kc2 < H_; kc2 += 32) {
        #pragma unroll
        for (int i = tid; i < 128 * 32; i += 256) {
            int r = i >> 5, c = i & 31;
            hs[r * 33 + c] = hid[(btb + r) * H_ + kc2 + c];
        }
        #pragma unroll
        for (int i = tid; i < 64 * 32; i += 256) {
            int r = i >> 5, c = i & 31;
            ws2[r * 33 + c] = Wout[r * H_ + kc2 + c];
        }
        __syncthreads();

        #pragma unroll 8
        for (int k = 0; k < 32; ++k) {
            float a[8], b[4];
            #pragma unroll
            for (int i = 0; i < 8; ++i) a[i] = hs[(ty + 16 * i) * 33 + k];
            #pragma unroll
            for (int j = 0; j < 4; ++j) b[j] = ws2[(tx + 16 * j) * 33 + k];
            #pragma unroll
            for (int i = 0; i < 8; ++i)
                #pragma unroll
                for (int j = 0; j < 4; ++j)
                    acc[i][j] += a[i] * b[j];
        }
        __syncthreads();
    }

    #pragma unroll
    for (int j = 0; j < 4; ++j) {
        int o = tx + 16 * j;
        float bb = bout[o];
        #pragma unroll
        for (int i = 0; i < 8; ++i)
            outp[(btb + ty + 16 * i) * O_ + o] = acc[i][j] + bb;
    }
}

// ---------------------------------------------------------------------------
extern "C" void kernel_launch(void* const* d_in, const int* in_sizes, int n_in,
                              void* d_out, int out_size) {
    const float* x      = (const float*)d_in[0];
    const float* hidden = (const float*)d_in[1];
    const float* W_ih   = (const float*)d_in[2];
    const float* W_hh   = (const float*)d_in[3];
    const float* b_ih   = (const float*)d_in[4];
    const float* b_hh   = (const float*)d_in[5];
    const float* W_out  = (const float*)d_in[6];
    const float* b_out  = (const float*)d_in[7];
    float* out = (float*)d_out;

    dim3 gA(H_ / 64, (B_ * T_) / 64);
    xw_kernel<<<gA, 256>>>(x, W_ih, b_ih, b_hh, out + HID_OFF);

    size_t smemB = (size_t)(48 * HR) * sizeof(float);   // 203,520 B
    cudaFuncSetAttribute(rnn_recur, cudaFuncAttributeMaxDynamicSharedMemorySize,
                         (int)smemB);
    rnn_recur<<<NBLK, TB, smemB>>>(hidden, W_hh, out);

    out_kernel<<<(B_ * T_) / 128, 256>>>(out + HID_OFF, W_out, b_out, out + OUT_OFF);
}

// round 3
// speedup vs baseline: 1.7615x; 1.1409x over previous
#include <cuda_runtime.h>

// ---------------------------------------------------------------------------
// Elman RNN (relu), B=64, T=512, I=64, H=1024, O=64
// out = [ hidden_list (B,T,H) | output_list (B,T,O) | h_last (1,B,H) ]
// ---------------------------------------------------------------------------

#define B_   64
#define T_   512
#define I_   64
#define H_   1024
#define O_   64

#define HID_OFF  0
#define OUT_OFF  (B_ * T_ * H_)              // 33554432
#define HL_OFF   (OUT_OFF + B_ * T_ * O_)    // 35651584

#define NBLK 128        // persistent blocks (1/SM)
#define TB   256        // threads per recurrence block (2 warps / SMSP)

// SMEM layout (floats): 32 K-chunks of 32 floats, each padded to 34
#define CH    34        // chunk stride: 32 + 2 (8-byte bank rotation per chunk)
#define HRow  1088      // row stride: 32 * 34
#define RST   34        // reduction row stride (per output, 32 partials + pad)

// scratch: h double buffer + per-batch-group barrier state
__device__ float    g_hbuf[2][B_ * H_];
__device__ unsigned g_cnt[4 * 32];     // one counter per batch group (padded)
__device__ unsigned g_gen2[4 * 32];

typedef unsigned long long ull;

__device__ __forceinline__ ull f2fma(ull a, ull b, ull c) {
    ull d;
    asm("fma.rn.f32x2 %0, %1, %2, %3;" : "=l"(d) : "l"(a), "l"(b), "l"(c));
    return d;
}
__device__ __forceinline__ ull f2add(ull a, ull b) {
    ull d;
    asm("add.rn.f32x2 %0, %1, %2;" : "=l"(d) : "l"(a), "l"(b));
    return d;
}
__device__ __forceinline__ float pairsum(ull a) {
    float lo = __uint_as_float((unsigned)(a & 0xffffffffull));
    float hi = __uint_as_float((unsigned)(a >> 32));
    return lo + hi;
}

// ---------------------------------------------------------------------------
// Kernel A: xw[bt][h] = x[bt]·W_ih[h] + b_ih[h] + b_hh[h]  -> hidden region
// ---------------------------------------------------------------------------
__global__ void __launch_bounds__(256) xw_kernel(
    const float* __restrict__ x, const float* __restrict__ Wih,
    const float* __restrict__ bih, const float* __restrict__ bhh,
    float* __restrict__ hid_out)
{
    __shared__ float xs[64 * 65];
    __shared__ float ws[64 * 65];

    const int tid = threadIdx.x;
    const int hb  = blockIdx.x * 64;
    const int btb = blockIdx.y * 64;

    #pragma unroll
    for (int i = tid; i < 64 * 64; i += 256) {
        int r = i >> 6, c = i & 63;
        xs[r * 65 + c] = x[(btb + r) * 64 + c];
        ws[r * 65 + c] = Wih[(hb + r) * 64 + c];
    }
    __syncthreads();

    const int tx = tid & 15, ty = tid >> 4;
    float acc[4][4] = {};

    #pragma unroll 8
    for (int k = 0; k < 64; ++k) {
        float a0 = xs[(ty     ) * 65 + k];
        float a1 = xs[(ty + 16) * 65 + k];
        float a2 = xs[(ty + 32) * 65 + k];
        float a3 = xs[(ty + 48) * 65 + k];
        float b0 = ws[(tx     ) * 65 + k];
        float b1 = ws[(tx + 16) * 65 + k];
        float b2 = ws[(tx + 32) * 65 + k];
        float b3 = ws[(tx + 48) * 65 + k];
        acc[0][0] += a0 * b0; acc[0][1] += a0 * b1; acc[0][2] += a0 * b2; acc[0][3] += a0 * b3;
        acc[1][0] += a1 * b0; acc[1][1] += a1 * b1; acc[1][2] += a1 * b2; acc[1][3] += a1 * b3;
        acc[2][0] += a2 * b0; acc[2][1] += a2 * b1; acc[2][2] += a2 * b2; acc[2][3] += a2 * b3;
        acc[3][0] += a3 * b0; acc[3][1] += a3 * b1; acc[3][2] += a3 * b2; acc[3][3] += a3 * b3;
    }

    #pragma unroll
    for (int j = 0; j < 4; ++j) {
        int h = hb + tx + 16 * j;
        float bb = bih[h] + bhh[h];
        #pragma unroll
        for (int i = 0; i < 4; ++i) {
            int bt = btb + ty + 16 * i;
            hid_out[bt * H_ + h] = acc[i][j] + bb;
        }
    }
}

// ---------------------------------------------------------------------------
// Kernel B: persistent recurrence.
// 128 blocks = 4 batch-groups(16 batches) x 32 col-groups(32 cols).
// tid -> kc = tid&31 (K-chunk of 32, spans the warp -> conflict-free LDS),
//        p  = tid>>5 (warp-uniform 8x8 tile position: pm batch octet, pn col octet)
// Each thread: 8x8 f32x2 tile over its private K-chunk, then 32-way
// output-major SMEM reduction, relu epilogue, per-batch-group grid barrier.
// ---------------------------------------------------------------------------
__global__ void __launch_bounds__(TB, 1) rnn_recur(
    const float* __restrict__ hid_in,
    const float* __restrict__ Whh,
    float* __restrict__ out)
{
    extern __shared__ float sm[];
    float* wsm = sm;                 // 32 rows x HRow  (~136 KB)
    float* hsm = sm + 32 * HRow;     // 16 rows x HRow  (~68 KB)
    float* red = hsm;                // reduction buffer aliases h staging

    const int tid = threadIdx.x;
    const int bi  = blockIdx.x >> 5;
    const int ci  = blockIdx.x & 31;
    const int b0  = bi * 16;
    const int c0  = ci * 32;

    const int kc = tid & 31;           // K-chunk (lane-spanning)
    const int p  = tid >> 5;           // warp-uniform tile position 0..7
    const int pm = p & 1;
    const int pn = p >> 1;

    // ---- stage W_hh slice once: rows c0..c0+31, chunked layout ----
    const float2* W2 = (const float2*)Whh;
    #pragma unroll 4
    for (int i = tid; i < 32 * 512; i += TB) {
        int r = i >> 9, q = i & 511;
        *(float2*)&wsm[r * HRow + (q >> 4) * CH + (q & 15) * 2] =
            __ldg(&W2[(c0 + r) * 512 + q]);
    }

    const float* hb_ = hsm + pm * 8 * HRow + kc * CH;
    const float* wb_ = wsm + pn * 8 * HRow + kc * CH;

    float* hid_out = out + HID_OFF;
    float* hlast   = out + HL_OFF;

    // epilogue mapping: thread owns outputs o = tid (b=tid>>5, c=tid&31)
    // and o+256 (b+8, same c)
    const int eb = tid >> 5;           // 0..7
    const int ec = tid & 31;
    const int gb0 = b0 + eb, gb1 = b0 + eb + 8;
    const int gc  = c0 + ec;

    for (int s = 0; s < T_; ++s) {
        // prefetch xw for this thread's two outputs
        float xw0 = __ldcg(&hid_out[((size_t)gb0 * T_ + s) * H_ + gc]);
        float xw1 = __ldcg(&hid_out[((size_t)gb1 * T_ + s) * H_ + gc]);

        // ---- stage h slice (16 x 1024) into chunked SMEM layout ----
        const float2* hsrc = (s == 0) ? (const float2*)hid_in
                                      : (const float2*)g_hbuf[(s - 1) & 1];
        #pragma unroll 8
        for (int i = tid; i < 16 * 512; i += TB) {
            int r = i >> 9, q = i & 511;
            *(float2*)&hsm[r * HRow + (q >> 4) * CH + (q & 15) * 2] =
                __ldcg(&hsrc[(b0 + r) * 512 + q]);
        }
        __syncthreads();

        // ---- 8x8 tile over private K-chunk of 32 ----
        ull acc[64];
        #pragma unroll
        for (int i = 0; i < 64; ++i) acc[i] = 0ull;

        #pragma unroll
        for (int k2 = 0; k2 < 16; ++k2) {
            ull hv[8];
            #pragma unroll
            for (int i = 0; i < 8; ++i)
                hv[i] = *(const ull*)(hb_ + i * HRow + k2 * 2);
            ull wv[4];
            #pragma unroll
            for (int j = 0; j < 4; ++j)
                wv[j] = *(const ull*)(wb_ + j * HRow + k2 * 2);
            #pragma unroll
            for (int i = 0; i < 8; ++i)
                #pragma unroll
                for (int j = 0; j < 4; ++j)
                    acc[i * 8 + j] = f2fma(hv[i], wv[j], acc[i * 8 + j]);
            #pragma unroll
            for (int j = 0; j < 4; ++j)
                wv[j] = *(const ull*)(wb_ + (j + 4) * HRow + k2 * 2);
            #pragma unroll
            for (int i = 0; i < 8; ++i)
                #pragma unroll
                for (int j = 0; j < 4; ++j)
                    acc[i * 8 + j + 4] = f2fma(hv[i], wv[j], acc[i * 8 + j + 4]);
        }
        __syncthreads();   // finish reading hsm before red overwrites it

        // ---- write partials, output-major: red[o*RST + kc] ----
        #pragma unroll
        for (int i = 0; i < 8; ++i)
            #pragma unroll
            for (int j = 0; j < 8; ++j) {
                int o = (pm * 8 + i) * 32 + pn * 8 + j;
                red[o * RST + kc] = pairsum(acc[i * 8 + j]);
            }
        __syncthreads();

        // ---- 32-way reduction: thread sums rows o=tid and o=tid+256 ----
        ull a0 = 0, a1 = 0;
        #pragma unroll
        for (int r = 0; r < 16; ++r) {
            a0 = f2add(a0, *(const ull*)&red[tid * RST + 2 * r]);
            a1 = f2add(a1, *(const ull*)&red[(tid + 256) * RST + 2 * r]);
        }
        float v0 = pairsum(a0);
        float v1 = pairsum(a1);

        float r0 = fmaxf(xw0 + v0, 0.0f);
        float r1 = fmaxf(xw1 + v1, 0.0f);

        hid_out[((size_t)gb0 * T_ + s) * H_ + gc] = r0;
        hid_out[((size_t)gb1 * T_ + s) * H_ + gc] = r1;
        float* hnew = g_hbuf[s & 1];
        hnew[gb0 * H_ + gc] = r0;
        hnew[gb1 * H_ + gc] = r1;
        if (s == T_ - 1) {
            hlast[gb0 * H_ + gc] = r0;
            hlast[gb1 * H_ + gc] = r1;
        }

        // ---- per-batch-group barrier (32 blocks), skip after last step ----
        if (s != T_ - 1) {
            __threadfence();
            __syncthreads();
            if (tid == 0) {
                volatile unsigned* gen = &g_gen2[bi * 32];
                unsigned my = *gen;
                if (atomicAdd(&g_cnt[bi * 32], 1) == 31) {
                    g_cnt[bi * 32] = 0;
                    __threadfence();
                    atomicAdd((unsigned*)gen, 1);
                } else {
                    while (*gen == my) { }
                }
            }
            __syncthreads();
        }
    }
}

// ---------------------------------------------------------------------------
// Kernel C: output_list[bt][o] = hid[bt]·W_out[o] + b_out[o]   (f32x2)
// M=32768, N=64, K=1024. Block tile 128x64, 256 threads, 8x4 tiles.
// ---------------------------------------------------------------------------
__global__ void __launch_bounds__(256) out_kernel(
    const float* __restrict__ hid, const float* __restrict__ Wout,
    const float* __restrict__ bout, float* __restrict__ outp)
{
    __shared__ float hs[128 * CH];    // 128 rows x 34
    __shared__ float ws2[64 * CH];    // 64 rows x 34

    const int tid = threadIdx.x;
    const int btb = blockIdx.x * 128;
    const int tx = tid & 15, ty = tid >> 4;

    const float2* hid2  = (const float2*)hid;
    const float2* wout2 = (const float2*)Wout;

    ull acc[8][4];
    #pragma unroll
    for (int i = 0; i < 8; ++i)
        #pragma unroll
        for (int j = 0; j < 4; ++j) acc[i][j] = 0ull;

    for (int kcb = 0; kcb < 512; kcb += 16) {      // float2 K-chunks of 16
        #pragma unroll
        for (int i = tid; i < 128 * 16; i += 256) {
            int r = i >> 4, q = i & 15;
            *(float2*)&hs[r * CH + q * 2] = hid2[(btb + r) * 512 + kcb + q];
        }
        #pragma unroll
        for (int i = tid; i < 64 * 16; i += 256) {
            int r = i >> 4, q = i & 15;
            *(float2*)&ws2[r * CH + q * 2] = wout2[r * 512 + kcb + q];
        }
        __syncthreads();

        #pragma unroll
        for (int k2 = 0; k2 < 16; ++k2) {
            ull a[8], b[4];
            #pragma unroll
            for (int i = 0; i < 8; ++i)
                a[i] = *(const ull*)&hs[(ty + 16 * i) * CH + k2 * 2];
            #pragma unroll
            for (int j = 0; j < 4; ++j)
                b[j] = *(const ull*)&ws2[(tx + 16 * j) * CH + k2 * 2];
            #pragma unroll
            for (int i = 0; i < 8; ++i)
                #pragma unroll
                for (int j = 0; j < 4; ++j)
                    acc[i][j] = f2fma(a[i], b[j], acc[i][j]);
        }
        __syncthreads();
    }

    #pragma unroll
    for (int j = 0; j < 4; ++j) {
        int o = tx + 16 * j;
        float bb = bout[o];
        #pragma unroll
        for (int i = 0; i < 8; ++i)
            outp[(btb + ty + 16 * i) * O_ + o] = pairsum(acc[i][j]) + bb;
    }
}

// ---------------------------------------------------------------------------
extern "C" void kernel_launch(void* const* d_in, const int* in_sizes, int n_in,
                              void* d_out, int out_size) {
    const float* x      = (const float*)d_in[0];
    const float* hidden = (const float*)d_in[1];
    const float* W_ih   = (const float*)d_in[2];
    const float* W_hh   = (const float*)d_in[3];
    const float* b_ih   = (const float*)d_in[4];
    const float* b_hh   = (const float*)d_in[5];
    const float* W_out  = (const float*)d_in[6];
    const float* b_out  = (const float*)d_in[7];
    float* out = (float*)d_out;

    dim3 gA(H_ / 64, (B_ * T_) / 64);
    xw_kernel<<<gA, 256>>>(x, W_ih, b_ih, b_hh, out + HID_OFF);

    size_t smemB = (size_t)(48 * HRow) * sizeof(float);   // 208,896 B
    cudaFuncSetAttribute(rnn_recur, cudaFuncAttributeMaxDynamicSharedMemorySize,
                         (int)smemB);
    rnn_recur<<<NBLK, TB, smemB>>>(hidden, W_hh, out);

    out_kernel<<<(B_ * T_) / 128, 256>>>(out + HID_OFF, W_out, b_out, out + OUT_OFF);
}